// round 3
// baseline (speedup 1.0000x reference)
#include <cuda_runtime.h>
#include <cuda_bf16.h>

#define KNN 32
#define MAXC 512          // max in-cutoff candidates per node (Poisson mean ~34)
#define NMAX 8192

__device__ int    g_starts[64];
__device__ float4 g_pq[NMAX];   // (p0, p1, p2, |p|^2)

// Kernel 1: pack pos + squared norm (reference rounding: (p0*p0 + p1*p1) + p2*p2,
// no FMA) and compute segment lower bounds for batch ids 0..8 (batch sorted int32).
__global__ void prep_kernel(const float* __restrict__ pos,
                            const int* __restrict__ batch, int N) {
    int tid = blockIdx.x * blockDim.x + threadIdx.x;
    int stride = gridDim.x * blockDim.x;
    for (int i = tid; i < N; i += stride) {
        float p0 = pos[3*i+0], p1 = pos[3*i+1], p2 = pos[3*i+2];
        float a = __fadd_rn(__fadd_rn(__fmul_rn(p0,p0), __fmul_rn(p1,p1)),
                            __fmul_rn(p2,p2));
        g_pq[i] = make_float4(p0, p1, p2, a);
    }
    if (blockIdx.x == 0 && threadIdx.x <= 8) {
        int b = (int)threadIdx.x;
        int lo = 0, hi = N;
        while (lo < hi) {
            int mid = (lo + hi) >> 1;
            if (batch[mid] < b) lo = mid + 1; else hi = mid;
        }
        g_starts[threadIdx.x] = lo;
    }
}

// Monotonic float->uint mapping (handles tiny negative d2 from gram-trick rounding)
__device__ __forceinline__ unsigned int f2mono(float f) {
    unsigned int u = __float_as_uint(f);
    return (u & 0x80000000u) ? ~u : (u | 0x80000000u);
}

// Kernel 2: one block per node. Scan same-batch segment, filter by cutoff,
// rank-select K nearest (tie -> lower index, matching jax.lax.top_k), write outputs.
__global__ void __launch_bounds__(128)
radius_graph_kernel(const int* __restrict__ batch,
                    float* __restrict__ out, int N) {
    const int i = blockIdx.x;

    __shared__ unsigned long long s_keys[MAXC];
    __shared__ unsigned long long s_sel[KNN];
    __shared__ int s_cnt;

    if (threadIdx.x == 0) s_cnt = 0;
    __syncthreads();

    const int b  = batch[i];
    const int lo = g_starts[b];
    const int hi = g_starts[b + 1];

    const float4 pc = g_pq[i];
    const float p0 = pc.x, p1 = pc.y, p2 = pc.z, x2i = pc.w;

    // Phase 1: scan segment, compact in-cutoff candidates.
    // d2 = (x2[i] + x2[j]) - 2*dot, dot as FMA chain -- mirrors reference gram trick.
    for (int j = lo + threadIdx.x; j < hi; j += blockDim.x) {
        if (j == i) continue;
        float4 q = g_pq[j];
        float dot = __fmaf_rn(p2, q.z, __fmaf_rn(p1, q.y, __fmul_rn(p0, q.x)));
        float d2  = __fsub_rn(__fadd_rn(x2i, q.w), __fmul_rn(2.0f, dot));
        if (d2 <= 100.0f) {   // CUTOFF^2
            int slot = atomicAdd(&s_cnt, 1);
            if (slot < MAXC) {
                s_keys[slot] = ((unsigned long long)f2mono(d2) << 32)
                             | (unsigned int)j;
            }
        }
    }
    __syncthreads();

    const int M = min(s_cnt, MAXC);

    // Phase 2: rank selection. Keys are unique (index in low bits), so ranks
    // form a permutation; element with rank k is the k-th nearest (tie->lower idx).
    for (int e = threadIdx.x; e < M; e += blockDim.x) {
        unsigned long long mykey = s_keys[e];
        int rank = 0;
        for (int t = 0; t < M; t++) rank += (s_keys[t] < mykey) ? 1 : 0;
        if (rank < KNN) s_sel[rank] = mykey;
    }
    __syncthreads();

    const int Msel = min(M, KNN);
    const long long E = (long long)N * (KNN + 1);

    // Phase 3: write the K neighbor slots for node i.
    for (int k = threadIdx.x; k < KNN; k += blockDim.x) {
        long long e = (long long)i * KNN + k;
        float rowf, w, mf;
        if (k < Msel) {
            int j = (int)(s_sel[k] & 0xFFFFFFFFull);
            rowf = (float)j;
            mf = 1.0f;
            // weight: direct difference, reference rounding: ((d0^2+d1^2)+d2^2), sqrt
            float4 q = g_pq[j];
            float d0 = __fsub_rn(q.x, p0);
            float d1 = __fsub_rn(q.y, p1);
            float d2v = __fsub_rn(q.z, p2);
            float sq = __fadd_rn(__fadd_rn(__fmul_rn(d0,d0), __fmul_rn(d1,d1)),
                                 __fmul_rn(d2v,d2v));
            w = (sq > 0.0f) ? __fsqrt_rn(sq) : 0.0f;
        } else {
            rowf = 0.0f; w = 0.0f; mf = 0.0f;
        }
        out[e]         = rowf;        // edge_index row
        out[E + e]     = (float)i;    // edge_index col
        out[2*E + e]   = w;           // edge_weight (mask already applied)
        out[3*E + e]   = mf;          // mask
    }

    // Self-loop appended at position N*K + i: row=col=i, mask=1, weight=0.
    if (threadIdx.x == 0) {
        long long e = (long long)N * KNN + i;
        out[e]       = (float)i;
        out[E + e]   = (float)i;
        out[2*E + e] = 0.0f;
        out[3*E + e] = 1.0f;
    }
}

extern "C" void kernel_launch(void* const* d_in, const int* in_sizes, int n_in,
                              void* d_out, int out_size) {
    const float* pos   = (const float*)d_in[0];
    const int*   batch = (const int*)d_in[1];
    float*       out   = (float*)d_out;

    int N = in_sizes[0] / 3;   // pos is [N,3] float32

    prep_kernel<<<32, 256>>>(pos, batch, N);
    radius_graph_kernel<<<N, 128>>>(batch, out, N);
}